// round 14
// baseline (speedup 1.0000x reference)
#include <cuda_runtime.h>
#include <math.h>

// Fixed problem: B=128, T=514, D=8, H=64, L=2, IN=17, W=512, N=65536
// out layout: [0,524288) residuals (B,W,D) | [524288,524416) logdet (B,)
//             [524416,8913024) hist_jac (D,N,16)
#define SLOPE 0.2f
#define SACT 132          // activation row stride
#define SW   68           // weight row stride

#define OFF_OUT 0          // [8][128] partial head sums (aliases X)
#define OFF_J   1024       // [64] logdet partials      (aliases X)
#define OFF_X   0          // [17][SACT] layer-0 inputs (dead after phase 2)
#define OFF_A   2244       // [64][SACT] ping
#define OFF_B   10692      // [64][SACT] pong
#define OFF_WA  19140      // [64][SW] weight buffer A
#define OFF_WB  23492      // [64][SW] weight buffer B
#define OFF_SB0 27844
#define OFF_SB1 27908
#define OFF_SB2 27972
#define OFF_SWO 28036
#define OFF_FLAG 28100
#define SMEM_FLOATS 28104
#define SMEM_BYTES  (SMEM_FLOATS * 4)

typedef unsigned long long u64;
typedef unsigned int u32;

__device__ float g_partials[4096];   // [d][tile]
__device__ u32   g_done = 0;

__device__ __forceinline__ u64 ffma2(u64 a, u64 b, u64 c) {
    u64 d; asm("fma.rn.f32x2 %0, %1, %2, %3;" : "=l"(d) : "l"(a), "l"(b), "l"(c)); return d;
}
__device__ __forceinline__ u64 pack2(float x, float y) {
    u64 r; asm("mov.b64 %0, {%1, %2};" : "=l"(r) : "f"(x), "f"(y)); return r;
}
__device__ __forceinline__ float2 unpk(u64 v) {
    float2 r; asm("mov.b64 {%0, %1}, %2;" : "=f"(r.x), "=f"(r.y) : "l"(v)); return r;
}
__device__ __forceinline__ float lk(float v) { return v > 0.f ? v : v * SLOPE; }
__device__ __forceinline__ float mb64(u64 m, int b) { return ((m >> b) & 1ull) ? 1.f : SLOPE; }

// ---- cp.async helpers (gmem -> smem, no registers) ----
__device__ __forceinline__ u32 smaddr(const void* p) {
    return (u32)__cvta_generic_to_shared(p);
}
#define CP16(dst, src) asm volatile("cp.async.cg.shared.global [%0], [%1], 16;" \
                                    :: "r"(smaddr(dst)), "l"(src))
#define CP4(dst, src)  asm volatile("cp.async.ca.shared.global [%0], [%1], 4;"  \
                                    :: "r"(smaddr(dst)), "l"(src))
#define CP_COMMIT()    asm volatile("cp.async.commit_group;")
#define CP_WAIT0()     asm volatile("cp.async.wait_group 0;" ::: "memory")

// Row-major weight stage via cp.async: dst [h][k] chunks of 16B. 128 threads.
#define CPASYNC_R(DST, SRC)                                                     \
    do {                                                                        \
        _Pragma("unroll")                                                       \
        for (int q = 0; q < 8; ++q) {                                           \
            int i4 = q * 128 + tid;                                             \
            CP16(sm + (DST) + (i4 >> 4) * SW + (i4 & 15) * 4,                   \
                 (SRC) + i4 * 4);                                               \
        }                                                                       \
        CP_COMMIT();                                                            \
    } while (0)

// Forward transposed staging, wave Wv (4 float4 -> [k][h]): LDG into pre[4].
#define PREF_W(SRC, Wv)                                                         \
    _Pragma("unroll")                                                           \
    for (int q = 0; q < 4; ++q)                                                 \
        pre[q] = ((const float4*)(SRC))[((Wv) * 4 + q) * 128 + tid];
#define STS_TRW(DST, Wv)                                                        \
    _Pragma("unroll")                                                           \
    for (int q = 0; q < 4; ++q) {                                               \
        int i4 = ((Wv) * 4 + q) * 128 + tid;                                    \
        int h = i4 >> 4, c4 = (i4 & 15) * 4;                                    \
        float* dp = sm + (DST) + h;                                             \
        dp[(c4 + 0) * SW] = pre[q].x;                                           \
        dp[(c4 + 1) * SW] = pre[q].y;                                           \
        dp[(c4 + 2) * SW] = pre[q].z;                                           \
        dp[(c4 + 3) * SW] = pre[q].w;                                           \
    }

// 8 outs (4 packed pairs, outs ob..ob+7 contiguous) x 8 samples per thread.
__device__ __forceinline__ void gemm8x8(const float* __restrict__ A,
                                        const float* __restrict__ Wp,
                                        int K, u64* acc) {
#pragma unroll 4
    for (int k = 0; k < K; ++k) {
        float4 aA = *(const float4*)(A + k * SACT);
        float4 aB = *(const float4*)(A + k * SACT + 4);
        ulonglong2 wA = *(const ulonglong2*)(Wp + k * SW);
        ulonglong2 wB = *(const ulonglong2*)(Wp + k * SW + 4);
        u64 a0 = pack2(aA.x, aA.x), a1 = pack2(aA.y, aA.y);
        u64 a2 = pack2(aA.z, aA.z), a3 = pack2(aA.w, aA.w);
        u64 a4 = pack2(aB.x, aB.x), a5 = pack2(aB.y, aB.y);
        u64 a6 = pack2(aB.z, aB.z), a7 = pack2(aB.w, aB.w);
        acc[0]  = ffma2(wA.x, a0, acc[0]);   acc[1]  = ffma2(wA.x, a1, acc[1]);
        acc[2]  = ffma2(wA.x, a2, acc[2]);   acc[3]  = ffma2(wA.x, a3, acc[3]);
        acc[4]  = ffma2(wA.x, a4, acc[4]);   acc[5]  = ffma2(wA.x, a5, acc[5]);
        acc[6]  = ffma2(wA.x, a6, acc[6]);   acc[7]  = ffma2(wA.x, a7, acc[7]);
        acc[8]  = ffma2(wA.y, a0, acc[8]);   acc[9]  = ffma2(wA.y, a1, acc[9]);
        acc[10] = ffma2(wA.y, a2, acc[10]);  acc[11] = ffma2(wA.y, a3, acc[11]);
        acc[12] = ffma2(wA.y, a4, acc[12]);  acc[13] = ffma2(wA.y, a5, acc[13]);
        acc[14] = ffma2(wA.y, a6, acc[14]);  acc[15] = ffma2(wA.y, a7, acc[15]);
        acc[16] = ffma2(wB.x, a0, acc[16]);  acc[17] = ffma2(wB.x, a1, acc[17]);
        acc[18] = ffma2(wB.x, a2, acc[18]);  acc[19] = ffma2(wB.x, a3, acc[19]);
        acc[20] = ffma2(wB.x, a4, acc[20]);  acc[21] = ffma2(wB.x, a5, acc[21]);
        acc[22] = ffma2(wB.x, a6, acc[22]);  acc[23] = ffma2(wB.x, a7, acc[23]);
        acc[24] = ffma2(wB.y, a0, acc[24]);  acc[25] = ffma2(wB.y, a1, acc[25]);
        acc[26] = ffma2(wB.y, a2, acc[26]);  acc[27] = ffma2(wB.y, a3, acc[27]);
        acc[28] = ffma2(wB.y, a4, acc[28]);  acc[29] = ffma2(wB.y, a5, acc[29]);
        acc[30] = ffma2(wB.y, a6, acc[30]);  acc[31] = ffma2(wB.y, a7, acc[31]);
    }
}

// Forward/backward activation epilogue: pair p -> rows ob+2p / ob+2p+1, cols sb..sb+7.
#define EPI_STORE(BUF, P, LO, HI)                                               \
    do {                                                                        \
        float* r0 = sm + (BUF) + (ob + 2 * (P)) * SACT + sb;                    \
        float* r1 = sm + (BUF) + (ob + 2 * (P) + 1) * SACT + sb;                \
        *(float4*)r0       = make_float4(LO[0], LO[1], LO[2], LO[3]);           \
        *(float4*)(r0 + 4) = make_float4(LO[4], LO[5], LO[6], LO[7]);           \
        *(float4*)r1       = make_float4(HI[0], HI[1], HI[2], HI[3]);           \
        *(float4*)(r1 + 4) = make_float4(HI[4], HI[5], HI[6], HI[7]);           \
    } while (0)

__global__ void __launch_bounds__(128, 2)
mlp_tile_kernel(const float* __restrict__ x,
                const float* __restrict__ W0, const float* __restrict__ b0,
                const float* __restrict__ W1, const float* __restrict__ b1,
                const float* __restrict__ W2, const float* __restrict__ b2,
                const float* __restrict__ Wo, const float* __restrict__ bo,
                float* __restrict__ out)
{
    extern __shared__ float sm[];
    const int tid  = threadIdx.x;     // 128 threads
    const int lane = tid & 31;
    const int warp = tid >> 5;        // 4 warps
    const int og   = lane & 7;        // out octet
    const int sg   = lane >> 3;       // sample octet
    const int ob   = og * 8;
    const int sb   = warp * 32 + sg * 8;
    const int tile = blockIdx.x;
    const int d    = blockIdx.y;

    const float bo_d = bo[d];

    // -------- phase 1: stage X, W0^T -> WA, biases --------
    {
        const int n = tile * 128 + tid;
        const float* xb = x + (size_t)((n >> 9) * 514 + (n & 511)) * 8;
        float4 v0 = *(const float4*)(xb);
        float4 v1 = *(const float4*)(xb + 4);
        float4 v2 = *(const float4*)(xb + 8);
        float4 v3 = *(const float4*)(xb + 12);
        float* dst = sm + OFF_X + tid;
        dst[0 * SACT]  = v0.x;  dst[1 * SACT]  = v0.y;
        dst[2 * SACT]  = v0.z;  dst[3 * SACT]  = v0.w;
        dst[4 * SACT]  = v1.x;  dst[5 * SACT]  = v1.y;
        dst[6 * SACT]  = v1.z;  dst[7 * SACT]  = v1.w;
        dst[8 * SACT]  = v2.x;  dst[9 * SACT]  = v2.y;
        dst[10 * SACT] = v2.z;  dst[11 * SACT] = v2.w;
        dst[12 * SACT] = v3.x;  dst[13 * SACT] = v3.y;
        dst[14 * SACT] = v3.z;  dst[15 * SACT] = v3.w;
        dst[16 * SACT] = xb[16 + d];
    }
    for (int i = tid; i < 1088; i += 128) {         // W0^T [k][h]
        int h = i / 17, k = i - 17 * h;
        sm[OFF_WA + k * SW + h] = W0[d * 1088 + i];
    }
    if (tid < 64) {
        sm[OFF_SB0 + tid] = b0[d * 64 + tid];
        sm[OFF_SB1 + tid] = b1[d * 64 + tid];
        sm[OFF_SB2 + tid] = b2[d * 64 + tid];
        sm[OFF_SWO + tid] = Wo[d * 64 + tid];
    }
    __syncthreads();

    u64 acc[32];
    u64 m0 = 0ull, m1 = 0ull;
    float4 pre[4];

    // -------- phase 2: L0 (X, WA) -> A; stage W1^T -> WB in 2 waves --------
    PREF_W(W1 + d * 4096, 0);
#pragma unroll
    for (int p = 0; p < 4; ++p) {
        u64 bp = *(const u64*)(sm + OFF_SB0 + ob + 2 * p);
#pragma unroll
        for (int j = 0; j < 8; ++j) acc[p * 8 + j] = bp;
    }
    gemm8x8(sm + OFF_X + sb, sm + OFF_WA + ob, 17, acc);
    STS_TRW(OFF_WB, 0);
    PREF_W(W1 + d * 4096, 1);
#pragma unroll
    for (int p = 0; p < 4; ++p) {
        float lo[8], hi[8];
#pragma unroll
        for (int j = 0; j < 8; ++j) {
            float2 v = unpk(acc[p * 8 + j]);
            m0 |= ((u64)(v.x > 0.f) << (p * 16 + 2 * j))
                | ((u64)(v.y > 0.f) << (p * 16 + 2 * j + 1));
            lo[j] = lk(v.x); hi[j] = lk(v.y);
        }
        EPI_STORE(OFF_A, p, lo, hi);
    }
    STS_TRW(OFF_WB, 1);
    __syncthreads();

    // -------- phase 3: L1 (A, WB) -> B; stage W2^T -> WA in 2 waves --------
    PREF_W(W2 + d * 4096, 0);
#pragma unroll
    for (int p = 0; p < 4; ++p) {
        u64 bp = *(const u64*)(sm + OFF_SB1 + ob + 2 * p);
#pragma unroll
        for (int j = 0; j < 8; ++j) acc[p * 8 + j] = bp;
    }
    gemm8x8(sm + OFF_A + sb, sm + OFF_WB + ob, 64, acc);
    STS_TRW(OFF_WA, 0);
    PREF_W(W2 + d * 4096, 1);
#pragma unroll
    for (int p = 0; p < 4; ++p) {
        float lo[8], hi[8];
#pragma unroll
        for (int j = 0; j < 8; ++j) {
            float2 v = unpk(acc[p * 8 + j]);
            m1 |= ((u64)(v.x > 0.f) << (p * 16 + 2 * j))
                | ((u64)(v.y > 0.f) << (p * 16 + 2 * j + 1));
            lo[j] = lk(v.x); hi[j] = lk(v.y);
        }
        EPI_STORE(OFF_B, p, lo, hi);
    }
    STS_TRW(OFF_WA, 1);
    __syncthreads();

    // -------- phase 4: L2 + head (B, WA) -> g in A; cp.async W2 rows -> WB --------
    CPASYNC_R(OFF_WB, W2 + d * 4096);
#pragma unroll
    for (int p = 0; p < 4; ++p) {
        u64 bp = *(const u64*)(sm + OFF_SB2 + ob + 2 * p);
#pragma unroll
        for (int j = 0; j < 8; ++j) acc[p * 8 + j] = bp;
    }
    gemm8x8(sm + OFF_B + sb, sm + OFF_WA + ob, 64, acc);
    {
        float osum[8];
#pragma unroll
        for (int j = 0; j < 8; ++j) osum[j] = 0.f;
#pragma unroll
        for (int p = 0; p < 4; ++p) {
            float wl = sm[OFF_SWO + ob + 2 * p];
            float wh = sm[OFF_SWO + ob + 2 * p + 1];
            float gl[8], gh[8];
#pragma unroll
            for (int j = 0; j < 8; ++j) {
                float2 v = unpk(acc[p * 8 + j]);
                gl[j] = wl * (v.x > 0.f ? 1.f : SLOPE);
                gh[j] = wh * (v.y > 0.f ? 1.f : SLOPE);
                osum[j] = fmaf(gl[j], v.x, fmaf(gh[j], v.y, osum[j]));
            }
            EPI_STORE(OFF_A, p, gl, gh);
        }
        float* po = sm + OFF_OUT + og * 128 + sb;
        *(float4*)po       = make_float4(osum[0], osum[1], osum[2], osum[3]);
        *(float4*)(po + 4) = make_float4(osum[4], osum[5], osum[6], osum[7]);
    }
    CP_WAIT0();
    __syncthreads();

    // -------- phase 5: residuals; bwd2 (A, WB)*m1 -> B; cp.async W1 rows -> WA --------
    CPASYNC_R(OFF_WA, W1 + d * 4096);
    {
        float r = bo_d;
#pragma unroll
        for (int q = 0; q < 8; ++q) r += sm[OFF_OUT + q * 128 + tid];
        out[(size_t)(tile * 128 + tid) * 8 + d] = r;
    }
#pragma unroll
    for (int i = 0; i < 32; ++i) acc[i] = 0ull;
    gemm8x8(sm + OFF_A + sb, sm + OFF_WB + ob, 64, acc);
#pragma unroll
    for (int p = 0; p < 4; ++p) {
        float lo[8], hi[8];
#pragma unroll
        for (int j = 0; j < 8; ++j) {
            float2 v = unpk(acc[p * 8 + j]);
            lo[j] = v.x * mb64(m1, p * 16 + 2 * j);
            hi[j] = v.y * mb64(m1, p * 16 + 2 * j + 1);
        }
        EPI_STORE(OFF_B, p, lo, hi);
    }
    CP_WAIT0();
    __syncthreads();

    // -------- phase 6: bwd1 (B, WA)*m0 -> A; cp.async W0 raw -> WB (4B grain) --------
#pragma unroll
    for (int q = 0; q < 9; ++q) {
        int i = q * 128 + tid;
        if (i < 1088) {
            int h = i / 17, c = i - 17 * h;
            CP4(sm + OFF_WB + h * SW + c, W0 + d * 1088 + i);
        }
    }
    CP_COMMIT();
#pragma unroll
    for (int i = 0; i < 32; ++i) acc[i] = 0ull;
    gemm8x8(sm + OFF_B + sb, sm + OFF_WA + ob, 64, acc);
#pragma unroll
    for (int p = 0; p < 4; ++p) {
        float lo[8], hi[8];
#pragma unroll
        for (int j = 0; j < 8; ++j) {
            float2 v = unpk(acc[p * 8 + j]);
            lo[j] = v.x * mb64(m0, p * 16 + 2 * j);
            hi[j] = v.y * mb64(m0, p * 16 + 2 * j + 1);
        }
        EPI_STORE(OFF_A, p, lo, hi);
    }
    CP_WAIT0();
    __syncthreads();

    // -------- phase 7: jac = g1 @ W0 (raw layout in WB) --------
    {
        const int tyj = tid >> 6;      // 0..1 -> jac cols tyj*8..+7
        const int txj = tid & 63;      // 2 samples
        u64 a2[8];
#pragma unroll
        for (int i = 0; i < 8; ++i) a2[i] = 0ull;
        const float* ap = sm + OFF_A + txj * 2;
        const float* wp = sm + OFF_WB + tyj * 8;
#pragma unroll 4
        for (int k = 0; k < 64; ++k) {
            float2 a = *(const float2*)(ap + k * SACT);
            ulonglong2 wA = *(const ulonglong2*)(wp + k * SW);
            ulonglong2 wB = *(const ulonglong2*)(wp + k * SW + 4);
            u64 a0 = pack2(a.x, a.x), a1 = pack2(a.y, a.y);
            a2[0] = ffma2(wA.x, a0, a2[0]);  a2[1] = ffma2(wA.x, a1, a2[1]);
            a2[2] = ffma2(wA.y, a0, a2[2]);  a2[3] = ffma2(wA.y, a1, a2[3]);
            a2[4] = ffma2(wB.x, a0, a2[4]);  a2[5] = ffma2(wB.x, a1, a2[5]);
            a2[6] = ffma2(wB.y, a0, a2[6]);  a2[7] = ffma2(wB.y, a1, a2[7]);
        }
#pragma unroll
        for (int j = 0; j < 2; ++j) {
            int n = tile * 128 + txj * 2 + j;
            float2 p0 = unpk(a2[0 + j]), p1 = unpk(a2[2 + j]);
            float2 p2 = unpk(a2[4 + j]), p3 = unpk(a2[6 + j]);
            float* dst = out + 524416 + ((size_t)d * 65536 + n) * 16 + tyj * 8;
            *(float4*)dst       = make_float4(p0.x, p0.y, p1.x, p1.y);
            *(float4*)(dst + 4) = make_float4(p2.x, p2.y, p3.x, p3.y);
        }
        if (tid < 64) {
            const float* apj = sm + OFF_A + tid * 2;
            const float* wpj = sm + OFF_WB + 16;
            float s0 = 0.f, s1 = 0.f;
#pragma unroll 4
            for (int k = 0; k < 64; ++k) {
                float wv = wpj[k * SW];
                float2 a = *(const float2*)(apj + k * SACT);
                s0 = fmaf(wv, a.x, s0);
                s1 = fmaf(wv, a.y, s1);
            }
            sm[OFF_J + tid] = logf(fabsf(s0)) + logf(fabsf(s1));
        }
    }
    __syncthreads();

    // -------- phase 8: publish partial; last block reduces logdet --------
    if (tid == 0) {
        float sj = 0.f;
#pragma unroll
        for (int q = 0; q < 64; ++q) sj += sm[OFF_J + q];
        g_partials[d * 512 + tile] = sj;
        __threadfence();
        u32 v = atomicAdd(&g_done, 1u);
        sm[OFF_FLAG] = (v == 4095u) ? 1.f : 0.f;
    }
    __syncthreads();
    if (sm[OFF_FLAG] != 0.f) {
        __threadfence();
        const int b = tid;
        float s = 0.f;
#pragma unroll
        for (int dd = 0; dd < 8; ++dd)
#pragma unroll
            for (int q = 0; q < 4; ++q)
                s += g_partials[dd * 512 + b * 4 + q];
        out[524288 + b] = s;
        if (tid == 0) g_done = 0;
    }
}

extern "C" void kernel_launch(void* const* d_in, const int* in_sizes, int n_in,
                              void* d_out, int out_size) {
    const float* x  = (const float*)d_in[0];
    const float* W0 = (const float*)d_in[1];
    const float* b0 = (const float*)d_in[2];
    const float* W1 = (const float*)d_in[3];
    const float* b1 = (const float*)d_in[4];
    const float* W2 = (const float*)d_in[5];
    const float* b2 = (const float*)d_in[6];
    const float* Wo = (const float*)d_in[7];
    const float* bo = (const float*)d_in[8];
    float* out = (float*)d_out;

    cudaFuncSetAttribute(mlp_tile_kernel,
                         cudaFuncAttributeMaxDynamicSharedMemorySize, SMEM_BYTES);
    dim3 grid(512, 8);
    mlp_tile_kernel<<<grid, 128, SMEM_BYTES>>>(x, W0, b0, W1, b1, W2, b2, Wo, bo, out);
}

// round 15
// speedup vs baseline: 1.3829x; 1.3829x over previous
#include <cuda_runtime.h>
#include <math.h>

// Fixed problem: B=128, T=514, D=8, H=64, L=2, IN=17, W=512, N=65536
// out layout: [0,524288) residuals (B,W,D) | [524288,524416) logdet (B,)
//             [524416,8913024) hist_jac (D,N,16)
#define SLOPE 0.2f
#define SACT 132          // activation row stride (128 samples + pad)
#define SW   68           // weight row stride (64 + pad)

// smem float offsets
#define OFF_OUT 0          // [8][128] partial head sums (reuses X region)
#define OFF_J   1024       // [32] logdet partials      (reuses X region)
#define OFF_X   0          // [17][SACT] layer-0 inputs (freed after layer 0)
#define OFF_A   2244       // [64][SACT] ping
#define OFF_B   10692      // [64][SACT] pong
#define OFF_WA  19140      // [64][SW] weight buffer A
#define OFF_WB  23492      // [64][SW] weight buffer B
#define OFF_SB0 27844
#define OFF_SB1 27908
#define OFF_SB2 27972
#define OFF_SWO 28036
#define OFF_FLAG 28100     // last-block flag
#define SMEM_FLOATS 28104
#define SMEM_BYTES  (SMEM_FLOATS * 4)

typedef unsigned long long u64;
typedef unsigned int u32;

__device__ float g_partials[4096];   // [d][tile] (8 x 512)
__device__ u32   g_done = 0;         // finished-block counter (reset by last block)

__device__ __forceinline__ u64 ffma2(u64 a, u64 b, u64 c) {
    u64 d; asm("fma.rn.f32x2 %0, %1, %2, %3;" : "=l"(d) : "l"(a), "l"(b), "l"(c)); return d;
}
__device__ __forceinline__ u64 pack2(float x, float y) {
    u64 r; asm("mov.b64 %0, {%1, %2};" : "=l"(r) : "f"(x), "f"(y)); return r;
}
__device__ __forceinline__ float2 unpk(u64 v) {
    float2 r; asm("mov.b64 {%0, %1}, %2;" : "=f"(r.x), "=f"(r.y) : "l"(v)); return r;
}
__device__ __forceinline__ float lk(float v) { return v > 0.f ? v : v * SLOPE; }
__device__ __forceinline__ float mb(u32 m, int b) { return ((m >> b) & 1u) ? 1.f : SLOPE; }

// 8 outputs (4 packed pairs) x 4 samples per thread.
// Per k: 1 act LDS.128 + 2 broadcast weight LDS.128 + 16 FFMA2.
__device__ __forceinline__ void gemm8x4(const float* __restrict__ A,
                                        const float* __restrict__ Wp,
                                        int K, int txs, int tys, u64* acc) {
    const float* ap = A + txs * 4;
    const float* wp = Wp + tys * 8;
#pragma unroll 4
    for (int k = 0; k < K; ++k) {
        float4 a = *(const float4*)(ap + k * SACT);
        ulonglong2 w01 = *(const ulonglong2*)(wp + k * SW);
        ulonglong2 w23 = *(const ulonglong2*)(wp + k * SW + 4);
        u64 a0 = pack2(a.x, a.x), a1 = pack2(a.y, a.y);
        u64 a2 = pack2(a.z, a.z), a3 = pack2(a.w, a.w);
        acc[0]  = ffma2(w01.x, a0, acc[0]);   acc[1]  = ffma2(w01.x, a1, acc[1]);
        acc[2]  = ffma2(w01.x, a2, acc[2]);   acc[3]  = ffma2(w01.x, a3, acc[3]);
        acc[4]  = ffma2(w01.y, a0, acc[4]);   acc[5]  = ffma2(w01.y, a1, acc[5]);
        acc[6]  = ffma2(w01.y, a2, acc[6]);   acc[7]  = ffma2(w01.y, a3, acc[7]);
        acc[8]  = ffma2(w23.x, a0, acc[8]);   acc[9]  = ffma2(w23.x, a1, acc[9]);
        acc[10] = ffma2(w23.x, a2, acc[10]);  acc[11] = ffma2(w23.x, a3, acc[11]);
        acc[12] = ffma2(w23.y, a0, acc[12]);  acc[13] = ffma2(w23.y, a1, acc[13]);
        acc[14] = ffma2(w23.y, a2, acc[14]);  acc[15] = ffma2(w23.y, a3, acc[15]);
    }
}

// Coalesced row-major prefetch: thread gets W[h][4c..4c+3], h=i4>>4, c=i4&15.
#define PREF_R(SRC)                                                        \
    _Pragma("unroll")                                                      \
    for (int q = 0; q < 4; ++q) pre[q] = ((const float4*)(SRC))[q * 256 + tid];
// Store as-is [h][k] (for backward gemms).
#define STS_R(DST)                                                         \
    _Pragma("unroll")                                                      \
    for (int q = 0; q < 4; ++q) {                                          \
        int i4 = q * 256 + tid;                                            \
        *(float4*)(sm + (DST) + (i4 >> 4) * SW + (i4 & 15) * 4) = pre[q];  \
    }
// Store transposed [k][h] (for forward gemms).
#define STS_TR(DST)                                                        \
    _Pragma("unroll")                                                      \
    for (int q = 0; q < 4; ++q) {                                          \
        int i4 = q * 256 + tid;                                            \
        int h = i4 >> 4, c4 = (i4 & 15) * 4;                               \
        float* dp = sm + (DST) + h;                                        \
        dp[(c4 + 0) * SW] = pre[q].x;                                      \
        dp[(c4 + 1) * SW] = pre[q].y;                                      \
        dp[(c4 + 2) * SW] = pre[q].z;                                      \
        dp[(c4 + 3) * SW] = pre[q].w;                                      \
    }

// Forward-activation epilogue for pair p: rows ob+2p (lo), ob+2p+1 (hi), 4 samples.
#define STORE_ACT(BUF, P, V0, V1, V2, V3, F)                                         \
    do {                                                                             \
        *(float4*)(sm + (BUF) + (tys * 8 + 2 * (P)) * SACT + txs * 4) =              \
            make_float4(F(V0.x), F(V1.x), F(V2.x), F(V3.x));                         \
        *(float4*)(sm + (BUF) + (tys * 8 + 2 * (P) + 1) * SACT + txs * 4) =          \
            make_float4(F(V0.y), F(V1.y), F(V2.y), F(V3.y));                         \
    } while (0)

__global__ void __launch_bounds__(256, 2)
mlp_tile_kernel(const float* __restrict__ x,
                const float* __restrict__ W0, const float* __restrict__ b0,
                const float* __restrict__ W1, const float* __restrict__ b1,
                const float* __restrict__ W2, const float* __restrict__ b2,
                const float* __restrict__ Wo, const float* __restrict__ bo,
                float* __restrict__ out)
{
    extern __shared__ float sm[];
    const int tid  = threadIdx.x;
    const int txs  = tid & 31;      // 4 samples (txs*4 ..+3)
    const int tys  = tid >> 5;      // 8 outputs (tys*8 ..+7); uniform per warp
    const int tile = blockIdx.x;    // 0..511 (128 samples)
    const int d    = blockIdx.y;

    const float bo_d = bo[d];

    // -------- phase 1: stage X, W0^T -> WA, biases --------
    {
        const int s = tid & 127, half = tid >> 7;
        const int n = tile * 128 + s;
        const float* xb = x + (size_t)((n >> 9) * 514 + (n & 511)) * 8;
        float4 v0 = *(const float4*)(xb + half * 8);
        float4 v1 = *(const float4*)(xb + half * 8 + 4);
        float* dst = sm + OFF_X + s;
        dst[(half * 8 + 0) * SACT] = v0.x;  dst[(half * 8 + 1) * SACT] = v0.y;
        dst[(half * 8 + 2) * SACT] = v0.z;  dst[(half * 8 + 3) * SACT] = v0.w;
        dst[(half * 8 + 4) * SACT] = v1.x;  dst[(half * 8 + 5) * SACT] = v1.y;
        dst[(half * 8 + 6) * SACT] = v1.z;  dst[(half * 8 + 7) * SACT] = v1.w;
        if (half == 0) dst[16 * SACT] = xb[16 + d];
    }
    for (int i = tid; i < 1088; i += 256) {         // W0^T [k][h]
        int h = i / 17, k = i - 17 * h;
        sm[OFF_WA + k * SW + h] = W0[d * 1088 + i];
    }
    if (tid < 64) {
        sm[OFF_SB0 + tid] = b0[d * 64 + tid];
        sm[OFF_SB1 + tid] = b1[d * 64 + tid];
        sm[OFF_SB2 + tid] = b2[d * 64 + tid];
        sm[OFF_SWO + tid] = Wo[d * 64 + tid];
    }
    __syncthreads();

    u64 acc[16];
    u32 m0 = 0, m1 = 0;
    float4 pre[4];

    // -------- phase 2: L0 (X, WA) -> A; prefetch W1 -> WB^T --------
    PREF_R(W1 + d * 4096);
#pragma unroll
    for (int p = 0; p < 4; ++p) {
        u64 bp = *(const u64*)(sm + OFF_SB0 + tys * 8 + 2 * p);
        acc[p * 4 + 0] = bp; acc[p * 4 + 1] = bp; acc[p * 4 + 2] = bp; acc[p * 4 + 3] = bp;
    }
    gemm8x4(sm + OFF_X, sm + OFF_WA, 17, txs, tys, acc);
#pragma unroll
    for (int p = 0; p < 4; ++p) {
        float2 v0 = unpk(acc[p * 4 + 0]), v1 = unpk(acc[p * 4 + 1]);
        float2 v2 = unpk(acc[p * 4 + 2]), v3 = unpk(acc[p * 4 + 3]);
        m0 |= ((u32)(v0.x > 0.f) << (p * 8 + 0)) | ((u32)(v0.y > 0.f) << (p * 8 + 1))
            | ((u32)(v1.x > 0.f) << (p * 8 + 2)) | ((u32)(v1.y > 0.f) << (p * 8 + 3))
            | ((u32)(v2.x > 0.f) << (p * 8 + 4)) | ((u32)(v2.y > 0.f) << (p * 8 + 5))
            | ((u32)(v3.x > 0.f) << (p * 8 + 6)) | ((u32)(v3.y > 0.f) << (p * 8 + 7));
        STORE_ACT(OFF_A, p, v0, v1, v2, v3, lk);
    }
    STS_TR(OFF_WB);
    __syncthreads();

    // -------- phase 3: L1 (A, WB) -> B; prefetch W2 -> WA^T --------
    PREF_R(W2 + d * 4096);
#pragma unroll
    for (int p = 0; p < 4; ++p) {
        u64 bp = *(const u64*)(sm + OFF_SB1 + tys * 8 + 2 * p);
        acc[p * 4 + 0] = bp; acc[p * 4 + 1] = bp; acc[p * 4 + 2] = bp; acc[p * 4 + 3] = bp;
    }
    gemm8x4(sm + OFF_A, sm + OFF_WB, 64, txs, tys, acc);
#pragma unroll
    for (int p = 0; p < 4; ++p) {
        float2 v0 = unpk(acc[p * 4 + 0]), v1 = unpk(acc[p * 4 + 1]);
        float2 v2 = unpk(acc[p * 4 + 2]), v3 = unpk(acc[p * 4 + 3]);
        m1 |= ((u32)(v0.x > 0.f) << (p * 8 + 0)) | ((u32)(v0.y > 0.f) << (p * 8 + 1))
            | ((u32)(v1.x > 0.f) << (p * 8 + 2)) | ((u32)(v1.y > 0.f) << (p * 8 + 3))
            | ((u32)(v2.x > 0.f) << (p * 8 + 4)) | ((u32)(v2.y > 0.f) << (p * 8 + 5))
            | ((u32)(v3.x > 0.f) << (p * 8 + 6)) | ((u32)(v3.y > 0.f) << (p * 8 + 7));
        STORE_ACT(OFF_B, p, v0, v1, v2, v3, lk);
    }
    STS_TR(OFF_WA);
    __syncthreads();

    // -------- phase 4: L2 + head (B, WA) -> g in A; prefetch W2 -> WB row --------
    PREF_R(W2 + d * 4096);
#pragma unroll
    for (int p = 0; p < 4; ++p) {
        u64 bp = *(const u64*)(sm + OFF_SB2 + tys * 8 + 2 * p);
        acc[p * 4 + 0] = bp; acc[p * 4 + 1] = bp; acc[p * 4 + 2] = bp; acc[p * 4 + 3] = bp;
    }
    gemm8x4(sm + OFF_B, sm + OFF_WA, 64, txs, tys, acc);
    {
        float4 osum = make_float4(0.f, 0.f, 0.f, 0.f);
#pragma unroll
        for (int p = 0; p < 4; ++p) {
            float wl = sm[OFF_SWO + tys * 8 + 2 * p];
            float wh = sm[OFF_SWO + tys * 8 + 2 * p + 1];
            float2 v0 = unpk(acc[p * 4 + 0]), v1 = unpk(acc[p * 4 + 1]);
            float2 v2 = unpk(acc[p * 4 + 2]), v3 = unpk(acc[p * 4 + 3]);
            float gl0 = wl * (v0.x > 0.f ? 1.f : SLOPE), gh0 = wh * (v0.y > 0.f ? 1.f : SLOPE);
            float gl1 = wl * (v1.x > 0.f ? 1.f : SLOPE), gh1 = wh * (v1.y > 0.f ? 1.f : SLOPE);
            float gl2 = wl * (v2.x > 0.f ? 1.f : SLOPE), gh2 = wh * (v2.y > 0.f ? 1.f : SLOPE);
            float gl3 = wl * (v3.x > 0.f ? 1.f : SLOPE), gh3 = wh * (v3.y > 0.f ? 1.f : SLOPE);
            osum.x = fmaf(gl0, v0.x, fmaf(gh0, v0.y, osum.x));
            osum.y = fmaf(gl1, v1.x, fmaf(gh1, v1.y, osum.y));
            osum.z = fmaf(gl2, v2.x, fmaf(gh2, v2.y, osum.z));
            osum.w = fmaf(gl3, v3.x, fmaf(gh3, v3.y, osum.w));
            *(float4*)(sm + OFF_A + (tys * 8 + 2 * p) * SACT + txs * 4) =
                make_float4(gl0, gl1, gl2, gl3);
            *(float4*)(sm + OFF_A + (tys * 8 + 2 * p + 1) * SACT + txs * 4) =
                make_float4(gh0, gh1, gh2, gh3);
        }
        *(float4*)(sm + OFF_OUT + tys * 128 + txs * 4) = osum;
    }
    STS_R(OFF_WB);
    __syncthreads();

    // -------- phase 5: residuals; bwd2 (A, WB)*m1 -> B; prefetch W1 -> WA row --------
    if (tid < 128) {
        float r = bo_d;
#pragma unroll
        for (int q = 0; q < 8; ++q) r += sm[OFF_OUT + q * 128 + tid];
        out[(size_t)(tile * 128 + tid) * 8 + d] = r;
    }
    PREF_R(W1 + d * 4096);
#pragma unroll
    for (int i = 0; i < 16; ++i) acc[i] = 0ull;
    gemm8x4(sm + OFF_A, sm + OFF_WB, 64, txs, tys, acc);
#pragma unroll
    for (int p = 0; p < 4; ++p) {
        float2 v0 = unpk(acc[p * 4 + 0]), v1 = unpk(acc[p * 4 + 1]);
        float2 v2 = unpk(acc[p * 4 + 2]), v3 = unpk(acc[p * 4 + 3]);
        *(float4*)(sm + OFF_B + (tys * 8 + 2 * p) * SACT + txs * 4) =
            make_float4(v0.x * mb(m1, p * 8 + 0), v1.x * mb(m1, p * 8 + 2),
                        v2.x * mb(m1, p * 8 + 4), v3.x * mb(m1, p * 8 + 6));
        *(float4*)(sm + OFF_B + (tys * 8 + 2 * p + 1) * SACT + txs * 4) =
            make_float4(v0.y * mb(m1, p * 8 + 1), v1.y * mb(m1, p * 8 + 3),
                        v2.y * mb(m1, p * 8 + 5), v3.y * mb(m1, p * 8 + 7));
    }
    STS_R(OFF_WA);
    __syncthreads();

    // -------- phase 6: bwd1 (B, WA)*m0 -> A; prefetch W0 row (17 cols) -> WB --------
    float w0pre[5];
#pragma unroll
    for (int q = 0; q < 5; ++q) {
        int i = q * 256 + tid;
        w0pre[q] = (i < 1088) ? W0[d * 1088 + i] : 0.f;
    }
#pragma unroll
    for (int i = 0; i < 16; ++i) acc[i] = 0ull;
    gemm8x4(sm + OFF_B, sm + OFF_WA, 64, txs, tys, acc);
#pragma unroll
    for (int p = 0; p < 4; ++p) {
        float2 v0 = unpk(acc[p * 4 + 0]), v1 = unpk(acc[p * 4 + 1]);
        float2 v2 = unpk(acc[p * 4 + 2]), v3 = unpk(acc[p * 4 + 3]);
        *(float4*)(sm + OFF_A + (tys * 8 + 2 * p) * SACT + txs * 4) =
            make_float4(v0.x * mb(m0, p * 8 + 0), v1.x * mb(m0, p * 8 + 2),
                        v2.x * mb(m0, p * 8 + 4), v3.x * mb(m0, p * 8 + 6));
        *(float4*)(sm + OFF_A + (tys * 8 + 2 * p + 1) * SACT + txs * 4) =
            make_float4(v0.y * mb(m0, p * 8 + 1), v1.y * mb(m0, p * 8 + 3),
                        v2.y * mb(m0, p * 8 + 5), v3.y * mb(m0, p * 8 + 7));
    }
#pragma unroll
    for (int q = 0; q < 5; ++q) {
        int i = q * 256 + tid;
        if (i < 1088) {
            int h = i / 17, c = i - 17 * h;
            sm[OFF_WB + h * SW + c] = w0pre[q];    // raw layout for jac phase
        }
    }
    __syncthreads();

    // -------- phase 7: jac = g1 @ W0 (4 samples/thread; warps 0-1 jac, warp 2 j16) --------
    {
        const int wj   = tid >> 5;       // warp index
        const int lj   = tid & 31;
        if (wj < 2) {
            // jac cols wj*8..+7 for samples lj*4..+3
            u64 a2[16];                  // [colpair p 0..3][sample j 0..3]
#pragma unroll
            for (int i = 0; i < 16; ++i) a2[i] = 0ull;
            const float* ap = sm + OFF_A + lj * 4;
            const float* wp = sm + OFF_WB + wj * 8;
#pragma unroll 4
            for (int k = 0; k < 64; ++k) {
                float4 a = *(const float4*)(ap + k * SACT);
                ulonglong2 wA = *(const ulonglong2*)(wp + k * SW);
                ulonglong2 wB = *(const ulonglong2*)(wp + k * SW + 4);
                u64 a0 = pack2(a.x, a.x), a1 = pack2(a.y, a.y);
                u64 a2v = pack2(a.z, a.z), a3 = pack2(a.w, a.w);
                a2[0]  = ffma2(wA.x, a0, a2[0]);   a2[1]  = ffma2(wA.x, a1, a2[1]);
                a2[2]  = ffma2(wA.x, a2v, a2[2]);  a2[3]  = ffma2(wA.x, a3, a2[3]);
                a2[4]  = ffma2(wA.y, a0, a2[4]);   a2[5]  = ffma2(wA.y, a1, a2[5]);
                a2[6]  = ffma2(wA.y, a2v, a2[6]);  a2[7]  = ffma2(wA.y, a3, a2[7]);
                a2[8]  = ffma2(wB.x, a0, a2[8]);   a2[9]  = ffma2(wB.x, a1, a2[9]);
                a2[10] = ffma2(wB.x, a2v, a2[10]); a2[11] = ffma2(wB.x, a3, a2[11]);
                a2[12] = ffma2(wB.y, a0, a2[12]);  a2[13] = ffma2(wB.y, a1, a2[13]);
                a2[14] = ffma2(wB.y, a2v, a2[14]); a2[15] = ffma2(wB.y, a3, a2[15]);
            }
#pragma unroll
            for (int j = 0; j < 4; ++j) {
                int n = tile * 128 + lj * 4 + j;
                float2 p0 = unpk(a2[0 + j]),  p1 = unpk(a2[4 + j]);
                float2 p2 = unpk(a2[8 + j]),  p3 = unpk(a2[12 + j]);
                float* dst = out + 524416 + ((size_t)d * 65536 + n) * 16 + wj * 8;
                *(float4*)dst       = make_float4(p0.x, p0.y, p1.x, p1.y);
                *(float4*)(dst + 4) = make_float4(p2.x, p2.y, p3.x, p3.y);
            }
        } else if (wj == 2) {
            // j16 = g1 . W0[:,16] for samples lj*4..+3
            const float* ap = sm + OFF_A + lj * 4;
            const float* wp = sm + OFF_WB + 16;
            u64 s01 = 0ull, s23 = 0ull;
#pragma unroll 4
            for (int k = 0; k < 64; ++k) {
                float wv = wp[k * SW];
                float4 a = *(const float4*)(ap + k * SACT);
                u64 wvv = pack2(wv, wv);
                s01 = ffma2(wvv, pack2(a.x, a.y), s01);
                s23 = ffma2(wvv, pack2(a.z, a.w), s23);
            }
            float2 v01 = unpk(s01), v23 = unpk(s23);
            sm[OFF_J + lj] = logf(fabsf(v01.x)) + logf(fabsf(v01.y)) +
                             logf(fabsf(v23.x)) + logf(fabsf(v23.y));
        }
    }
    __syncthreads();

    // -------- phase 8: publish partial; last block does the logdet reduce --------
    if (tid == 0) {
        float sj = 0.f;
#pragma unroll
        for (int q = 0; q < 32; ++q) sj += sm[OFF_J + q];
        g_partials[d * 512 + tile] = sj;
        __threadfence();
        u32 v = atomicAdd(&g_done, 1u);
        sm[OFF_FLAG] = (v == 4095u) ? 1.f : 0.f;
    }
    __syncthreads();
    if (sm[OFF_FLAG] != 0.f) {
        __threadfence();   // acquire: all g_partials writes are visible
        if (tid < 128) {
            const int b = tid;
            float s = 0.f;
#pragma unroll
            for (int dd = 0; dd < 8; ++dd)
#pragma unroll
                for (int q = 0; q < 4; ++q)
                    s += g_partials[dd * 512 + b * 4 + q];
            out[524288 + b] = s;
        }
        if (tid == 0) g_done = 0;   // reset for next graph replay
    }
}

extern "C" void kernel_launch(void* const* d_in, const int* in_sizes, int n_in,
                              void* d_out, int out_size) {
    const float* x  = (const float*)d_in[0];
    const float* W0 = (const float*)d_in[1];
    const float* b0 = (const float*)d_in[2];
    const float* W1 = (const float*)d_in[3];
    const float* b1 = (const float*)d_in[4];
    const float* W2 = (const float*)d_in[5];
    const float* b2 = (const float*)d_in[6];
    const float* Wo = (const float*)d_in[7];
    const float* bo = (const float*)d_in[8];
    float* out = (float*)d_out;

    cudaFuncSetAttribute(mlp_tile_kernel,
                         cudaFuncAttributeMaxDynamicSharedMemorySize, SMEM_BYTES);
    dim3 grid(512, 8);
    mlp_tile_kernel<<<grid, 256, SMEM_BYTES>>>(x, W0, b0, W1, b1, W2, b2, Wo, bo, out);
}